// round 1
// baseline (speedup 1.0000x reference)
#include <cuda_runtime.h>
#include <math.h>

// Problem constants (fixed by the dataset)
#define NN   50000
#define NE   1600000
#define NQ_  500000
#define DIN  128
#define DHID 128
#define DOUT 64
#define DFCH 256

// ---------------- scratch (device globals; no allocation allowed) ----------
static __device__ __align__(16) float g_H1[NN * DHID];   // x @ W1
static __device__ __align__(16) float g_A1[NN * DHID];   // relu(agg1)
static __device__ __align__(16) float g_H2[NN * DOUT];   // A1 @ W2
static __device__ __align__(16) float g_G [NN * DOUT];   // agg2 + b2  (gcn out)
static __device__ __align__(16) float g_F1[NN * DFCH];   // relu(x@Wf1+bf1)
static __device__ __align__(16) float g_Z [NN * DOUT];   // 0.5*gcn + 0.5*fc
static __device__ int   g_cnt[NN];
static __device__ int   g_rowptr[NN + 1];
static __device__ int   g_cursor[NN];
static __device__ int   g_col[NE];
static __device__ float g_dinv[NN];

// ---------------- CSR build -------------------------------------------------
__global__ void zero_k(int n) {
    int i = blockIdx.x * blockDim.x + threadIdx.x;
    if (i < n) g_cnt[i] = 0;
}

__global__ void hist_k(const int* __restrict__ dst, int ne) {
    int e = blockIdx.x * blockDim.x + threadIdx.x;
    if (e < ne) atomicAdd(&g_cnt[dst[e]], 1);
}

// single-block exclusive scan of g_cnt -> g_rowptr/g_cursor; also dinv = rsqrt(cnt+1)
__global__ void scan_k(int n) {
    __shared__ int sm[1024];
    int t = threadIdx.x;
    int offset = 0;
    for (int base = 0; base < n; base += 1024) {
        int idx = base + t;
        int v = (idx < n) ? g_cnt[idx] : 0;
        sm[t] = v;
        __syncthreads();
        for (int d = 1; d < 1024; d <<= 1) {
            int add = (t >= d) ? sm[t - d] : 0;
            __syncthreads();
            sm[t] += add;
            __syncthreads();
        }
        int incl = sm[t];
        if (idx < n) {
            int excl = offset + incl - v;
            g_rowptr[idx] = excl;
            g_cursor[idx] = excl;
            g_dinv[idx]   = rsqrtf((float)(v + 1));   // +1 self loop
        }
        offset += sm[1023];
        __syncthreads();
    }
    if (t == 0) g_rowptr[n] = offset;
}

__global__ void fill_k(const int* __restrict__ ei, int ne) {
    int e = blockIdx.x * blockDim.x + threadIdx.x;
    if (e < ne) {
        int s = ei[e];
        int d = ei[ne + e];
        int p = atomicAdd(&g_cursor[d], 1);
        g_col[p] = s;
    }
}

// ---------------- GEMM: C[n x NO] = A[n x K] @ W[K x NO] (+bias,relu,combine)
template <int K, int NO, bool BIAS, bool RELU, bool COMBINE>
__global__ void __launch_bounds__(256) gemm_k(const float* __restrict__ A,
                                              const float* __restrict__ W,
                                              const float* __restrict__ bias,
                                              const float* __restrict__ other,
                                              float* __restrict__ C, int nRows) {
    constexpr int BM = 64, BK = 32, TM = 4;
    constexpr int CG = 16;           // column groups
    constexpr int TN = NO / CG;      // 4 / 8 / 16
    __shared__ float As[BK][BM];     // A^T tile
    __shared__ float Ws[BK][NO];

    const int tid = threadIdx.x;
    const int tx = tid % CG;
    const int ty = tid / CG;
    const int rowBase = blockIdx.x * BM;

    float acc[TM][TN];
#pragma unroll
    for (int r = 0; r < TM; r++)
#pragma unroll
        for (int c = 0; c < TN; c++) acc[r][c] = 0.f;

    for (int k0 = 0; k0 < K; k0 += BK) {
        // load A tile (64x32), transposed into smem
#pragma unroll
        for (int i = 0; i < 2; i++) {
            int id = tid + i * 256;          // 0..511 float4 slots
            int r  = id >> 3;
            int c4 = id & 7;
            float4 v = make_float4(0.f, 0.f, 0.f, 0.f);
            int grow = rowBase + r;
            if (grow < nRows) v = *(const float4*)&A[(size_t)grow * K + k0 + c4 * 4];
            As[c4 * 4 + 0][r] = v.x;
            As[c4 * 4 + 1][r] = v.y;
            As[c4 * 4 + 2][r] = v.z;
            As[c4 * 4 + 3][r] = v.w;
        }
        // load W tile (32 x NO)
        constexpr int WF4 = BK * NO / 4;
#pragma unroll
        for (int i = 0; i < WF4 / 256; i++) {
            int id = tid + i * 256;
            int r  = id / (NO / 4);
            int c4 = id % (NO / 4);
            *(float4*)&Ws[r][c4 * 4] = *(const float4*)&W[(size_t)(k0 + r) * NO + c4 * 4];
        }
        __syncthreads();
#pragma unroll
        for (int kk = 0; kk < BK; kk++) {
            float4 a4 = *(const float4*)&As[kk][ty * TM];
            float av[TM] = {a4.x, a4.y, a4.z, a4.w};
            float wv[TN];
#pragma unroll
            for (int c = 0; c < TN; c += 4) {
                float4 w4 = *(const float4*)&Ws[kk][tx * TN + c];
                wv[c] = w4.x; wv[c + 1] = w4.y; wv[c + 2] = w4.z; wv[c + 3] = w4.w;
            }
#pragma unroll
            for (int r = 0; r < TM; r++)
#pragma unroll
                for (int c = 0; c < TN; c++) acc[r][c] += av[r] * wv[c];
        }
        __syncthreads();
    }

#pragma unroll
    for (int r = 0; r < TM; r++) {
        int grow = rowBase + ty * TM + r;
        if (grow >= nRows) continue;
#pragma unroll
        for (int c = 0; c < TN; c += 4) {
            int col = tx * TN + c;
            float4 v = make_float4(acc[r][c], acc[r][c + 1], acc[r][c + 2], acc[r][c + 3]);
            if (BIAS) {
                v.x += bias[col]; v.y += bias[col + 1];
                v.z += bias[col + 2]; v.w += bias[col + 3];
            }
            if (RELU) {
                v.x = fmaxf(v.x, 0.f); v.y = fmaxf(v.y, 0.f);
                v.z = fmaxf(v.z, 0.f); v.w = fmaxf(v.w, 0.f);
            }
            if (COMBINE) {
                float4 o = *(const float4*)&other[(size_t)grow * NO + col];
                v.x = 0.5f * v.x + 0.5f * o.x;
                v.y = 0.5f * v.y + 0.5f * o.y;
                v.z = 0.5f * v.z + 0.5f * o.z;
                v.w = 0.5f * v.w + 0.5f * o.w;
            }
            *(float4*)&C[(size_t)grow * NO + col] = v;
        }
    }
}

// ---------------- pull aggregation: one warp per node ----------------------
// Out[i] = maybe_relu( dinv[i] * ( sum_{e in(i)} dinv[s]*H[s] + dinv[i]*H[i] ) + b )
template <int F, bool RELU>
__global__ void __launch_bounds__(256) agg_k(const float* __restrict__ H,
                                             const float* __restrict__ bias,
                                             float* __restrict__ Out, int n) {
    int gw = (blockIdx.x * 256 + threadIdx.x) >> 5;
    int lane = threadIdx.x & 31;
    if (gw >= n) return;
    constexpr int FPT = F / 32;        // 4 or 2
    const int colb = lane * FPT;
    const float di = g_dinv[gw];

    float acc[FPT];
    if constexpr (FPT == 4) {
        float4 v = *(const float4*)&H[(size_t)gw * F + colb];
        acc[0] = di * v.x; acc[1] = di * v.y; acc[2] = di * v.z; acc[3] = di * v.w;
    } else {
        float2 v = *(const float2*)&H[(size_t)gw * F + colb];
        acc[0] = di * v.x; acc[1] = di * v.y;
    }

    int e = g_rowptr[gw];
    const int end = g_rowptr[gw + 1];
    for (; e < end; e++) {
        int s = g_col[e];
        float d = g_dinv[s];
        if constexpr (FPT == 4) {
            float4 v = *(const float4*)&H[(size_t)s * F + colb];
            acc[0] += d * v.x; acc[1] += d * v.y; acc[2] += d * v.z; acc[3] += d * v.w;
        } else {
            float2 v = *(const float2*)&H[(size_t)s * F + colb];
            acc[0] += d * v.x; acc[1] += d * v.y;
        }
    }

#pragma unroll
    for (int j = 0; j < FPT; j++) {
        float o = di * acc[j] + bias[colb + j];
        if (RELU) o = fmaxf(o, 0.f);
        acc[j] = o;
    }
    if constexpr (FPT == 4)
        *(float4*)&Out[(size_t)gw * F + colb] = make_float4(acc[0], acc[1], acc[2], acc[3]);
    else
        *(float2*)&Out[(size_t)gw * F + colb] = make_float2(acc[0], acc[1]);
}

// ---------------- decode: out[q] = dot(z[a], z[b]) over 64 dims ------------
__global__ void __launch_bounds__(256) decode_k(const int* __restrict__ eli,
                                                const float* __restrict__ z,
                                                float* __restrict__ out, int nq) {
    int t = blockIdx.x * 256 + threadIdx.x;
    int q = t >> 4;
    int l = t & 15;
    if (q >= nq) return;
    int a = eli[q];
    int b = eli[nq + q];
    float4 va = *(const float4*)&z[(size_t)a * DOUT + l * 4];
    float4 vb = *(const float4*)&z[(size_t)b * DOUT + l * 4];
    float p = va.x * vb.x + va.y * vb.y + va.z * vb.z + va.w * vb.w;
    p += __shfl_xor_sync(0xffffffffu, p, 8);
    p += __shfl_xor_sync(0xffffffffu, p, 4);
    p += __shfl_xor_sync(0xffffffffu, p, 2);
    p += __shfl_xor_sync(0xffffffffu, p, 1);
    if (l == 0) out[q] = p;
}

// ---------------- launch ----------------------------------------------------
extern "C" void kernel_launch(void* const* d_in, const int* in_sizes, int n_in,
                              void* d_out, int out_size) {
    const float* x   = (const float*)d_in[0];
    const int*   ei  = (const int*)d_in[1];
    const int*   eli = (const int*)d_in[2];
    const float* W1  = (const float*)d_in[3];
    const float* b1  = (const float*)d_in[4];
    const float* W2  = (const float*)d_in[5];
    const float* b2  = (const float*)d_in[6];
    const float* Wf1 = (const float*)d_in[7];
    const float* bf1 = (const float*)d_in[8];
    const float* Wf2 = (const float*)d_in[9];
    const float* bf2 = (const float*)d_in[10];
    float* out = (float*)d_out;

    const int n  = in_sizes[0] / DIN;
    const int ne = in_sizes[1] / 2;
    const int nq = in_sizes[2] / 2;

    float *pH1, *pA1, *pH2, *pG, *pF1, *pZ;
    cudaGetSymbolAddress((void**)&pH1, g_H1);
    cudaGetSymbolAddress((void**)&pA1, g_A1);
    cudaGetSymbolAddress((void**)&pH2, g_H2);
    cudaGetSymbolAddress((void**)&pG,  g_G);
    cudaGetSymbolAddress((void**)&pF1, g_F1);
    cudaGetSymbolAddress((void**)&pZ,  g_Z);

    // 1. CSR build
    zero_k<<<(n + 255) / 256, 256>>>(n);
    hist_k<<<(ne + 255) / 256, 256>>>(ei + ne, ne);
    scan_k<<<1, 1024>>>(n);
    fill_k<<<(ne + 255) / 256, 256>>>(ei, ne);

    const int gb = (n + 63) / 64;
    const int ab128 = (n * 32 + 255) / 256;  // warp-per-node grids
    // 2. GCN layer 1
    gemm_k<DIN, DHID, false, false, false><<<gb, 256>>>(x, W1, nullptr, nullptr, pH1, n);
    agg_k<DHID, true><<<ab128, 256>>>(pH1, b1, pA1, n);
    // 3. GCN layer 2
    gemm_k<DHID, DOUT, false, false, false><<<gb, 256>>>(pA1, W2, nullptr, nullptr, pH2, n);
    agg_k<DOUT, false><<<ab128, 256>>>(pH2, b2, pG, n);
    // 4. FC branch + combine into z
    gemm_k<DIN, DFCH, true, true, false><<<gb, 256>>>(x, Wf1, bf1, nullptr, pF1, n);
    gemm_k<DFCH, DOUT, true, false, true><<<gb, 256>>>(pF1, Wf2, bf2, pG, pZ, n);
    // 5. edge dot-product decode
    decode_k<<<(nq * 16 + 255) / 256, 256>>>(eli, pZ, out, nq);
}

// round 2
// speedup vs baseline: 1.7071x; 1.7071x over previous
#include <cuda_runtime.h>
#include <math.h>

// Problem constants (fixed by the dataset)
#define NN   50000
#define NE   1600000
#define DIN  128
#define DHID 128
#define DOUT 64
#define DFCH 256

// ---------------- scratch (device globals; no allocation allowed) ----------
static __device__ __align__(16) float g_H1[NN * DHID];   // x @ W1 (raw)
static __device__ __align__(16) float g_A1[NN * DHID];   // relu(agg1 + b1)
static __device__ __align__(16) float g_H2[NN * DOUT];   // A1 @ W2 (raw)
static __device__ __align__(16) float g_G [NN * DOUT];   // agg2 + b2  (gcn out)
static __device__ __align__(16) float g_F1[NN * DFCH];   // relu(x@Wf1+bf1)
static __device__ __align__(16) float g_Z [NN * DOUT];   // 0.5*gcn + 0.5*fc
static __device__ int   g_cnt[NN];
static __device__ int   g_rowptr[NN + 1];
static __device__ int   g_cursor[NN];
static __device__ int   g_col[NE];
static __device__ float g_dinv[NN];
static __device__ int   g_bsum[256];                     // block sums for scan

// ---------------- CSR build -------------------------------------------------
__global__ void hist4_k(const int* __restrict__ dst, int ne) {
    int base = (blockIdx.x * blockDim.x + threadIdx.x) * 4;
    if (base + 4 <= ne) {
        int4 d = *(const int4*)&dst[base];
        atomicAdd(&g_cnt[d.x], 1);
        atomicAdd(&g_cnt[d.y], 1);
        atomicAdd(&g_cnt[d.z], 1);
        atomicAdd(&g_cnt[d.w], 1);
    } else {
        for (int e = base; e < ne; e++) atomicAdd(&g_cnt[dst[e]], 1);
    }
}
__global__ void hist_k(const int* __restrict__ dst, int ne) {
    int e = blockIdx.x * blockDim.x + threadIdx.x;
    if (e < ne) atomicAdd(&g_cnt[dst[e]], 1);
}

// scan stage 1: per-block reduce of counts
__global__ void reduce_k(int n) {
    __shared__ int sm[256];
    int t = threadIdx.x;
    int i = blockIdx.x * 256 + t;
    sm[t] = (i < n) ? g_cnt[i] : 0;
    __syncthreads();
    for (int d = 128; d > 0; d >>= 1) {
        if (t < d) sm[t] += sm[t + d];
        __syncthreads();
    }
    if (t == 0) g_bsum[blockIdx.x] = sm[0];
}

// scan stage 2: single-block scan of <=256 block sums
__global__ void scanb_k(int nb, int n) {
    __shared__ int sm[256];
    int t = threadIdx.x;
    int v = (t < nb) ? g_bsum[t] : 0;
    sm[t] = v;
    __syncthreads();
    for (int d = 1; d < 256; d <<= 1) {
        int a = (t >= d) ? sm[t - d] : 0;
        __syncthreads();
        sm[t] += a;
        __syncthreads();
    }
    if (t < nb) g_bsum[t] = sm[t] - v;     // exclusive
    if (t == 0) g_rowptr[n] = sm[255];     // total edges
}

// scan stage 3: local exclusive scan + block offset; also dinv
__global__ void scane_k(int n) {
    __shared__ int sm[256];
    int t = threadIdx.x;
    int i = blockIdx.x * 256 + t;
    int v = (i < n) ? g_cnt[i] : 0;
    sm[t] = v;
    __syncthreads();
    for (int d = 1; d < 256; d <<= 1) {
        int a = (t >= d) ? sm[t - d] : 0;
        __syncthreads();
        sm[t] += a;
        __syncthreads();
    }
    if (i < n) {
        int excl = g_bsum[blockIdx.x] + sm[t] - v;
        g_rowptr[i] = excl;
        g_cursor[i] = excl;
        g_dinv[i]   = rsqrtf((float)(v + 1));   // +1 self loop
    }
}

__global__ void fill4_k(const int* __restrict__ ei, int ne) {
    int base = (blockIdx.x * blockDim.x + threadIdx.x) * 4;
    if (base + 4 <= ne) {
        int4 s = *(const int4*)&ei[base];
        int4 d = *(const int4*)&ei[ne + base];
        g_col[atomicAdd(&g_cursor[d.x], 1)] = s.x;
        g_col[atomicAdd(&g_cursor[d.y], 1)] = s.y;
        g_col[atomicAdd(&g_cursor[d.z], 1)] = s.z;
        g_col[atomicAdd(&g_cursor[d.w], 1)] = s.w;
    } else {
        for (int e = base; e < ne; e++) {
            int sv = ei[e];
            int dv = ei[ne + e];
            g_col[atomicAdd(&g_cursor[dv], 1)] = sv;
        }
    }
}
__global__ void fill_k(const int* __restrict__ ei, int ne) {
    int e = blockIdx.x * blockDim.x + threadIdx.x;
    if (e < ne) {
        int s = ei[e];
        int d = ei[ne + e];
        g_col[atomicAdd(&g_cursor[d], 1)] = s;
    }
}

// ---------------- GEMM: C[n x N] = A[n x K] @ W[K x N] ---------------------
// BM=128, BK=16, 256 threads (16x16), thread tile 8 x TN (TN = BN/16).
template <int K, int N, int BN, bool BIAS, bool RELU, bool COMBINE>
__global__ void __launch_bounds__(256, 2) gemm_k(const float* __restrict__ A,
                                                 const float* __restrict__ W,
                                                 const float* __restrict__ bias,
                                                 const float* __restrict__ other,
                                                 float* __restrict__ C, int nRows) {
    constexpr int BM = 128, BK = 16;
    constexpr int TN = BN / 16;
    __shared__ float As[BK][BM + 4];
    __shared__ float Ws[BK][BN + 4];

    const int tid = threadIdx.x;
    const int tx = tid & 15;
    const int ty = tid >> 4;
    const int rowBase = blockIdx.x * BM;
    const int colBase = blockIdx.y * BN;

    float acc[8][TN];
#pragma unroll
    for (int r = 0; r < 8; r++)
#pragma unroll
        for (int c = 0; c < TN; c++) acc[r][c] = 0.f;

    for (int k0 = 0; k0 < K; k0 += BK) {
        // A tile: 128 x 16 -> transposed smem
#pragma unroll
        for (int i = 0; i < 2; i++) {
            int id = tid + i * 256;        // 0..511
            int row = id >> 2;
            int c4 = id & 3;
            float4 v = make_float4(0.f, 0.f, 0.f, 0.f);
            int grow = rowBase + row;
            if (grow < nRows) v = *(const float4*)&A[(size_t)grow * K + k0 + c4 * 4];
            As[c4 * 4 + 0][row] = v.x;
            As[c4 * 4 + 1][row] = v.y;
            As[c4 * 4 + 2][row] = v.z;
            As[c4 * 4 + 3][row] = v.w;
        }
        // W tile: 16 x BN
#pragma unroll
        for (int i = 0; i < BN / 64; i++) {
            int id = tid + i * 256;
            int r  = id / (BN / 4);
            int c4 = id % (BN / 4);
            *(float4*)&Ws[r][c4 * 4] =
                *(const float4*)&W[(size_t)(k0 + r) * N + colBase + c4 * 4];
        }
        __syncthreads();
#pragma unroll
        for (int kk = 0; kk < BK; kk++) {
            float4 a0 = *(const float4*)&As[kk][ty * 8];
            float4 a1 = *(const float4*)&As[kk][ty * 8 + 4];
            float av[8] = {a0.x, a0.y, a0.z, a0.w, a1.x, a1.y, a1.z, a1.w};
            float wv[TN];
#pragma unroll
            for (int c = 0; c < TN; c += 4) {
                float4 b = *(const float4*)&Ws[kk][tx * TN + c];
                wv[c] = b.x; wv[c + 1] = b.y; wv[c + 2] = b.z; wv[c + 3] = b.w;
            }
#pragma unroll
            for (int r = 0; r < 8; r++)
#pragma unroll
                for (int c = 0; c < TN; c++) acc[r][c] += av[r] * wv[c];
        }
        __syncthreads();
    }

    float bfrag[TN];
    if (BIAS) {
#pragma unroll
        for (int c = 0; c < TN; c++) bfrag[c] = bias[colBase + tx * TN + c];
    }
#pragma unroll
    for (int r = 0; r < 8; r++) {
        int grow = rowBase + ty * 8 + r;
        if (grow >= nRows) continue;
#pragma unroll
        for (int c = 0; c < TN; c += 4) {
            int col = colBase + tx * TN + c;
            float4 v = make_float4(acc[r][c], acc[r][c + 1], acc[r][c + 2], acc[r][c + 3]);
            if (BIAS) {
                v.x += bfrag[c]; v.y += bfrag[c + 1];
                v.z += bfrag[c + 2]; v.w += bfrag[c + 3];
            }
            if (RELU) {
                v.x = fmaxf(v.x, 0.f); v.y = fmaxf(v.y, 0.f);
                v.z = fmaxf(v.z, 0.f); v.w = fmaxf(v.w, 0.f);
            }
            if (COMBINE) {
                float4 o = *(const float4*)&other[(size_t)grow * N + col];
                v.x = 0.5f * v.x + 0.5f * o.x;
                v.y = 0.5f * v.y + 0.5f * o.y;
                v.z = 0.5f * v.z + 0.5f * o.z;
                v.w = 0.5f * v.w + 0.5f * o.w;
            }
            *(float4*)&C[(size_t)grow * N + col] = v;
        }
    }
}

// ---- fused layer-1 GEMM: [H1 | F1] = x @ [W1 | Wf1] -----------------------
// blockIdx.y: 0 -> H1 cols 0..127 (raw);  1,2 -> F1 cols 0..255 (bias+relu)
__global__ void __launch_bounds__(256, 2) fused1_k(const float* __restrict__ x,
                                                   const float* __restrict__ W1,
                                                   const float* __restrict__ Wf1,
                                                   const float* __restrict__ bf1,
                                                   float* __restrict__ H1,
                                                   float* __restrict__ F1, int nRows) {
    constexpr int BM = 128, BK = 16, BN = 128, TN = 8, K = DIN;
    __shared__ float As[BK][BM + 4];
    __shared__ float Ws[BK][BN + 4];

    const int tid = threadIdx.x;
    const int tx = tid & 15;
    const int ty = tid >> 4;
    const int rowBase = blockIdx.x * BM;
    const int cb = blockIdx.y;

    const float* Wp;
    int wN, colOff;
    if (cb == 0) { Wp = W1;  wN = DHID; colOff = 0; }
    else         { Wp = Wf1; wN = DFCH; colOff = (cb - 1) * 128; }

    float acc[8][TN];
#pragma unroll
    for (int r = 0; r < 8; r++)
#pragma unroll
        for (int c = 0; c < TN; c++) acc[r][c] = 0.f;

    for (int k0 = 0; k0 < K; k0 += BK) {
#pragma unroll
        for (int i = 0; i < 2; i++) {
            int id = tid + i * 256;
            int row = id >> 2;
            int c4 = id & 3;
            float4 v = make_float4(0.f, 0.f, 0.f, 0.f);
            int grow = rowBase + row;
            if (grow < nRows) v = *(const float4*)&x[(size_t)grow * K + k0 + c4 * 4];
            As[c4 * 4 + 0][row] = v.x;
            As[c4 * 4 + 1][row] = v.y;
            As[c4 * 4 + 2][row] = v.z;
            As[c4 * 4 + 3][row] = v.w;
        }
#pragma unroll
        for (int i = 0; i < 2; i++) {
            int id = tid + i * 256;
            int r  = id >> 5;          // /32
            int c4 = id & 31;
            *(float4*)&Ws[r][c4 * 4] =
                *(const float4*)&Wp[(size_t)(k0 + r) * wN + colOff + c4 * 4];
        }
        __syncthreads();
#pragma unroll
        for (int kk = 0; kk < BK; kk++) {
            float4 a0 = *(const float4*)&As[kk][ty * 8];
            float4 a1 = *(const float4*)&As[kk][ty * 8 + 4];
            float av[8] = {a0.x, a0.y, a0.z, a0.w, a1.x, a1.y, a1.z, a1.w};
            float4 b0 = *(const float4*)&Ws[kk][tx * TN];
            float4 b1 = *(const float4*)&Ws[kk][tx * TN + 4];
            float wv[8] = {b0.x, b0.y, b0.z, b0.w, b1.x, b1.y, b1.z, b1.w};
#pragma unroll
            for (int r = 0; r < 8; r++)
#pragma unroll
                for (int c = 0; c < TN; c++) acc[r][c] += av[r] * wv[c];
        }
        __syncthreads();
    }

    if (cb == 0) {
#pragma unroll
        for (int r = 0; r < 8; r++) {
            int grow = rowBase + ty * 8 + r;
            if (grow >= nRows) continue;
#pragma unroll
            for (int c = 0; c < TN; c += 4) {
                float4 v = make_float4(acc[r][c], acc[r][c + 1], acc[r][c + 2], acc[r][c + 3]);
                *(float4*)&H1[(size_t)grow * DHID + tx * TN + c] = v;
            }
        }
    } else {
        float bfrag[TN];
#pragma unroll
        for (int c = 0; c < TN; c++) bfrag[c] = bf1[colOff + tx * TN + c];
#pragma unroll
        for (int r = 0; r < 8; r++) {
            int grow = rowBase + ty * 8 + r;
            if (grow >= nRows) continue;
#pragma unroll
            for (int c = 0; c < TN; c += 4) {
                float4 v = make_float4(fmaxf(acc[r][c] + bfrag[c], 0.f),
                                       fmaxf(acc[r][c + 1] + bfrag[c + 1], 0.f),
                                       fmaxf(acc[r][c + 2] + bfrag[c + 2], 0.f),
                                       fmaxf(acc[r][c + 3] + bfrag[c + 3], 0.f));
                *(float4*)&F1[(size_t)grow * DFCH + colOff + tx * TN + c] = v;
            }
        }
    }
}

// ---------------- pull aggregation: one warp per node ----------------------
template <int F, bool RELU>
__global__ void __launch_bounds__(256) agg_k(const float* __restrict__ H,
                                             const float* __restrict__ bias,
                                             float* __restrict__ Out, int n) {
    int gw = (blockIdx.x * 256 + threadIdx.x) >> 5;
    int lane = threadIdx.x & 31;
    if (gw >= n) return;
    constexpr int FPT = F / 32;        // 4 or 2
    const int colb = lane * FPT;
    const float di = g_dinv[gw];

    float acc[FPT];
    if constexpr (FPT == 4) {
        float4 v = *(const float4*)&H[(size_t)gw * F + colb];
        acc[0] = di * v.x; acc[1] = di * v.y; acc[2] = di * v.z; acc[3] = di * v.w;
    } else {
        float2 v = *(const float2*)&H[(size_t)gw * F + colb];
        acc[0] = di * v.x; acc[1] = di * v.y;
    }

    int e = g_rowptr[gw];
    const int end = g_rowptr[gw + 1];
    for (; e < end; e++) {
        int s = __ldg(&g_col[e]);
        float d = __ldg(&g_dinv[s]);
        if constexpr (FPT == 4) {
            float4 v = *(const float4*)&H[(size_t)s * F + colb];
            acc[0] += d * v.x; acc[1] += d * v.y; acc[2] += d * v.z; acc[3] += d * v.w;
        } else {
            float2 v = *(const float2*)&H[(size_t)s * F + colb];
            acc[0] += d * v.x; acc[1] += d * v.y;
        }
    }

#pragma unroll
    for (int j = 0; j < FPT; j++) {
        float o = di * acc[j] + bias[colb + j];
        if (RELU) o = fmaxf(o, 0.f);
        acc[j] = o;
    }
    if constexpr (FPT == 4)
        *(float4*)&Out[(size_t)gw * F + colb] = make_float4(acc[0], acc[1], acc[2], acc[3]);
    else
        *(float2*)&Out[(size_t)gw * F + colb] = make_float2(acc[0], acc[1]);
}

// ---------------- decode: out[q] = dot(z[a], z[b]) over 64 dims ------------
__global__ void __launch_bounds__(256) decode_k(const int* __restrict__ eli,
                                                const float* __restrict__ z,
                                                float* __restrict__ out, int nq) {
    int t = blockIdx.x * 256 + threadIdx.x;
    int q = t >> 4;
    int l = t & 15;
    if (q >= nq) return;
    int a = eli[q];
    int b = eli[nq + q];
    float4 va = *(const float4*)&z[(size_t)a * DOUT + l * 4];
    float4 vb = *(const float4*)&z[(size_t)b * DOUT + l * 4];
    float p = va.x * vb.x + va.y * vb.y + va.z * vb.z + va.w * vb.w;
    p += __shfl_xor_sync(0xffffffffu, p, 8);
    p += __shfl_xor_sync(0xffffffffu, p, 4);
    p += __shfl_xor_sync(0xffffffffu, p, 2);
    p += __shfl_xor_sync(0xffffffffu, p, 1);
    if (l == 0) out[q] = p;
}

// ---------------- launch ----------------------------------------------------
extern "C" void kernel_launch(void* const* d_in, const int* in_sizes, int n_in,
                              void* d_out, int out_size) {
    const float* x   = (const float*)d_in[0];
    const int*   ei  = (const int*)d_in[1];
    const int*   eli = (const int*)d_in[2];
    const float* W1  = (const float*)d_in[3];
    const float* b1  = (const float*)d_in[4];
    const float* W2  = (const float*)d_in[5];
    const float* b2  = (const float*)d_in[6];
    const float* Wf1 = (const float*)d_in[7];
    const float* bf1 = (const float*)d_in[8];
    const float* Wf2 = (const float*)d_in[9];
    const float* bf2 = (const float*)d_in[10];
    float* out = (float*)d_out;

    const int n  = in_sizes[0] / DIN;
    const int ne = in_sizes[1] / 2;
    const int nq = in_sizes[2] / 2;

    float *pH1, *pA1, *pH2, *pG, *pF1, *pZ;
    int* pcnt;
    cudaGetSymbolAddress((void**)&pH1, g_H1);
    cudaGetSymbolAddress((void**)&pA1, g_A1);
    cudaGetSymbolAddress((void**)&pH2, g_H2);
    cudaGetSymbolAddress((void**)&pG,  g_G);
    cudaGetSymbolAddress((void**)&pF1, g_F1);
    cudaGetSymbolAddress((void**)&pZ,  g_Z);
    cudaGetSymbolAddress((void**)&pcnt, g_cnt);

    // 1. CSR build
    cudaMemsetAsync(pcnt, 0, (size_t)n * sizeof(int));
    if ((ne & 3) == 0)
        hist4_k<<<(ne / 4 + 255) / 256, 256>>>(ei + ne, ne);
    else
        hist_k<<<(ne + 255) / 256, 256>>>(ei + ne, ne);
    const int nb = (n + 255) / 256;
    reduce_k<<<nb, 256>>>(n);
    scanb_k<<<1, 256>>>(nb, n);
    scane_k<<<nb, 256>>>(n);
    if ((ne & 3) == 0)
        fill4_k<<<(ne / 4 + 255) / 256, 256>>>(ei, ne);
    else
        fill_k<<<(ne + 255) / 256, 256>>>(ei, ne);

    const int mb = (n + 127) / 128;
    const int ab = (n * 32 + 255) / 256;  // warp-per-node grid
    // 2. fused layer-1 transform: H1 = x@W1 (raw), F1 = relu(x@Wf1+bf1)
    fused1_k<<<dim3(mb, 3), 256>>>(x, W1, Wf1, bf1, pH1, pF1, n);
    // 3. GCN layer 1 aggregation -> A1
    agg_k<DHID, true><<<ab, 256>>>(pH1, b1, pA1, n);
    // 4. GCN layer 2
    gemm_k<DHID, DOUT, 64, false, false, false><<<dim3(mb, 1), 256>>>(pA1, W2, nullptr, nullptr, pH2, n);
    agg_k<DOUT, false><<<ab, 256>>>(pH2, b2, pG, n);
    // 5. FC layer 2 + combine into z
    gemm_k<DFCH, DOUT, 64, true, false, true><<<dim3(mb, 1), 256>>>(pF1, Wf2, bf2, pG, pZ, n);
    // 6. edge dot-product decode
    decode_k<<<(nq * 16 + 255) / 256, 256>>>(eli, pZ, out, nq);
}

// round 4
// speedup vs baseline: 2.3546x; 1.3793x over previous
#include <cuda_runtime.h>
#include <cuda_fp16.h>
#include <math.h>
#include <stdint.h>

// Problem constants (fixed by the dataset)
#define NN   50000
#define NE   1600000
#define DIN  128
#define DHID 128
#define DOUT 64
#define DFCH 256

// ---------------- scratch (device globals; no allocation allowed) ----------
static __device__ __align__(16) __half g_H1h[NN * DHID];  // x @ W1 (tf32), fp16
static __device__ __align__(16) float  g_A1[NN * DHID];   // relu(agg1 + b1)
static __device__ __align__(16) __half g_H2h[NN * DOUT];  // A1 @ W2, fp16
static __device__ __align__(16) float  g_G [NN * DOUT];   // agg2 + b2 (gcn out)
static __device__ __align__(16) float  g_F1[NN * DFCH];   // relu(x@Wf1+bf1)
static __device__ __align__(16) float  g_Z [NN * DOUT];   // 0.5*gcn + 0.5*fc
static __device__ int   g_cnt[NN];
static __device__ int   g_rowptr[NN + 1];
static __device__ int   g_cursor[NN];
static __device__ int   g_col[NE];
static __device__ float g_dinv[NN];
static __device__ int   g_bsum[256];

// ---------------- CSR build -------------------------------------------------
__global__ void hist4_k(const int* __restrict__ dst, int ne) {
    int base = (blockIdx.x * blockDim.x + threadIdx.x) * 4;
    if (base + 4 <= ne) {
        int4 d = *(const int4*)&dst[base];
        atomicAdd(&g_cnt[d.x], 1);
        atomicAdd(&g_cnt[d.y], 1);
        atomicAdd(&g_cnt[d.z], 1);
        atomicAdd(&g_cnt[d.w], 1);
    } else {
        for (int e = base; e < ne; e++) atomicAdd(&g_cnt[dst[e]], 1);
    }
}
__global__ void hist_k(const int* __restrict__ dst, int ne) {
    int e = blockIdx.x * blockDim.x + threadIdx.x;
    if (e < ne) atomicAdd(&g_cnt[dst[e]], 1);
}

__global__ void reduce_k(int n) {
    __shared__ int sm[256];
    int t = threadIdx.x;
    int i = blockIdx.x * 256 + t;
    sm[t] = (i < n) ? g_cnt[i] : 0;
    __syncthreads();
    for (int d = 128; d > 0; d >>= 1) {
        if (t < d) sm[t] += sm[t + d];
        __syncthreads();
    }
    if (t == 0) g_bsum[blockIdx.x] = sm[0];
}

__global__ void scanb_k(int nb, int n) {
    __shared__ int sm[256];
    int t = threadIdx.x;
    int v = (t < nb) ? g_bsum[t] : 0;
    sm[t] = v;
    __syncthreads();
    for (int d = 1; d < 256; d <<= 1) {
        int a = (t >= d) ? sm[t - d] : 0;
        __syncthreads();
        sm[t] += a;
        __syncthreads();
    }
    if (t < nb) g_bsum[t] = sm[t] - v;
    if (t == 0) g_rowptr[n] = sm[255];
}

__global__ void scane_k(int n) {
    __shared__ int sm[256];
    int t = threadIdx.x;
    int i = blockIdx.x * 256 + t;
    int v = (i < n) ? g_cnt[i] : 0;
    sm[t] = v;
    __syncthreads();
    for (int d = 1; d < 256; d <<= 1) {
        int a = (t >= d) ? sm[t - d] : 0;
        __syncthreads();
        sm[t] += a;
        __syncthreads();
    }
    if (i < n) {
        int excl = g_bsum[blockIdx.x] + sm[t] - v;
        g_rowptr[i] = excl;
        g_cursor[i] = excl;
        g_dinv[i]   = rsqrtf((float)(v + 1));
    }
}

__global__ void fill4_k(const int* __restrict__ ei, int ne) {
    int base = (blockIdx.x * blockDim.x + threadIdx.x) * 4;
    if (base + 4 <= ne) {
        int4 s = *(const int4*)&ei[base];
        int4 d = *(const int4*)&ei[ne + base];
        g_col[atomicAdd(&g_cursor[d.x], 1)] = s.x;
        g_col[atomicAdd(&g_cursor[d.y], 1)] = s.y;
        g_col[atomicAdd(&g_cursor[d.z], 1)] = s.z;
        g_col[atomicAdd(&g_cursor[d.w], 1)] = s.w;
    } else {
        for (int e = base; e < ne; e++) {
            int sv = ei[e];
            int dv = ei[ne + e];
            g_col[atomicAdd(&g_cursor[dv], 1)] = sv;
        }
    }
}
__global__ void fill_k(const int* __restrict__ ei, int ne) {
    int e = blockIdx.x * blockDim.x + threadIdx.x;
    if (e < ne) {
        int s = ei[e];
        int d = ei[ne + e];
        g_col[atomicAdd(&g_cursor[d], 1)] = s;
    }
}

// ---------------- TF32 helpers ---------------------------------------------
__device__ __forceinline__ float f2tf32(float f) {
    uint32_t u;
    asm("cvt.rna.tf32.f32 %0, %1;" : "=r"(u) : "f"(f));
    return __uint_as_float(u);
}

__device__ __forceinline__ void mma_tf32(float* d, const uint32_t* a, const uint32_t* b) {
    asm volatile(
        "mma.sync.aligned.m16n8k8.row.col.f32.tf32.tf32.f32 "
        "{%0,%1,%2,%3}, {%4,%5,%6,%7}, {%8,%9}, {%0,%1,%2,%3};"
        : "+f"(d[0]), "+f"(d[1]), "+f"(d[2]), "+f"(d[3])
        : "r"(a[0]), "r"(a[1]), "r"(a[2]), "r"(a[3]), "r"(b[0]), "r"(b[1]));
}

// ---------------- TF32 tensor-core GEMM ------------------------------------
// C[nRows x N] = A[nRows x K] @ W[K x N].  BM=128, BK=32, 256 threads.
// Warp layout: 4 (M) x 2 (N). Warp tile: 32 x (BN/2). mma m16n8k8.
template <int K, int N, int BN, bool BIAS, bool RELU, bool COMBINE, bool HALF_OUT>
__global__ void __launch_bounds__(256, 2) mmagemm_k(const float* __restrict__ A,
                                                    const float* __restrict__ W,
                                                    const float* __restrict__ bias,
                                                    const float* __restrict__ other,
                                                    void* __restrict__ Cv, int nRows) {
    constexpr int BM = 128, BK = 32;
    constexpr int AS_STRIDE = BK + 4;              // 36: bank = lane for a-frags
    constexpr int WS_STRIDE = BN + 8;              // mod 32 == 8: conflict-free b-frags
    constexpr int NT = BN / 16;                    // n8-tiles per warp (8 or 4)
    __shared__ float As[BM * AS_STRIDE];
    __shared__ float Ws[BK * WS_STRIDE];

    const int tid = threadIdx.x;
    const int lane = tid & 31;
    const int wid = tid >> 5;
    const int warpM = wid & 3;                     // 0..3 -> 32-row slab
    const int warpN = wid >> 2;                    // 0..1 -> (BN/2)-col slab
    const int rowBase = blockIdx.x * BM;
    const int colBase = blockIdx.y * BN;

    float acc[2][NT][4];
#pragma unroll
    for (int mt = 0; mt < 2; mt++)
#pragma unroll
        for (int nt = 0; nt < NT; nt++)
#pragma unroll
            for (int i = 0; i < 4; i++) acc[mt][nt][i] = 0.f;

    for (int k0 = 0; k0 < K; k0 += BK) {
        // A tile: BM x BK, row-major smem stride 36, tf32-rounded
#pragma unroll
        for (int i = 0; i < 4; i++) {
            int s = tid + i * 256;                 // float4 slot 0..1023
            int m = s >> 3;
            int c4 = (s & 7) * 4;
            float4 v = make_float4(0.f, 0.f, 0.f, 0.f);
            int grow = rowBase + m;
            if (grow < nRows) v = *(const float4*)&A[(size_t)grow * K + k0 + c4];
            float* p = &As[m * AS_STRIDE + c4];
            p[0] = f2tf32(v.x); p[1] = f2tf32(v.y);
            p[2] = f2tf32(v.z); p[3] = f2tf32(v.w);
        }
        // W tile: BK x BN, row-major smem stride BN+8, tf32-rounded
#pragma unroll
        for (int i = 0; i < BN / 32; i++) {
            int s = tid + i * 256;                 // float4 slot
            int r = s / (BN / 4);
            int c4 = (s % (BN / 4)) * 4;
            float4 v = *(const float4*)&W[(size_t)(k0 + r) * N + colBase + c4];
            float* p = &Ws[r * WS_STRIDE + c4];
            p[0] = f2tf32(v.x); p[1] = f2tf32(v.y);
            p[2] = f2tf32(v.z); p[3] = f2tf32(v.w);
        }
        __syncthreads();

#pragma unroll
        for (int ks = 0; ks < BK / 8; ks++) {
            const int k8 = ks * 8;
            uint32_t a[2][4];
#pragma unroll
            for (int mt = 0; mt < 2; mt++) {
                const float* Ap = &As[(warpM * 32 + mt * 16 + (lane >> 2)) * AS_STRIDE
                                      + k8 + (lane & 3)];
                a[mt][0] = __float_as_uint(Ap[0]);
                a[mt][1] = __float_as_uint(Ap[8 * AS_STRIDE]);
                a[mt][2] = __float_as_uint(Ap[4]);
                a[mt][3] = __float_as_uint(Ap[8 * AS_STRIDE + 4]);
            }
#pragma unroll
            for (int nt = 0; nt < NT; nt++) {
                const int n0 = warpN * (NT * 8) + nt * 8 + (lane >> 2);
                uint32_t b[2];
                b[0] = __float_as_uint(Ws[(k8 + (lane & 3)) * WS_STRIDE + n0]);
                b[1] = __float_as_uint(Ws[(k8 + (lane & 3) + 4) * WS_STRIDE + n0]);
                mma_tf32(acc[0][nt], a[0], b);
                mma_tf32(acc[1][nt], a[1], b);
            }
        }
        __syncthreads();
    }

    // epilogue: each thread owns pairs (c, c+1) at rows r and r+8 per (mt, nt)
#pragma unroll
    for (int mt = 0; mt < 2; mt++) {
#pragma unroll
        for (int half = 0; half < 2; half++) {
            int row = rowBase + warpM * 32 + mt * 16 + (lane >> 2) + half * 8;
            if (row >= nRows) continue;
#pragma unroll
            for (int nt = 0; nt < NT; nt++) {
                int col = colBase + warpN * (NT * 8) + nt * 8 + (lane & 3) * 2;
                float v0 = acc[mt][nt][half * 2 + 0];
                float v1 = acc[mt][nt][half * 2 + 1];
                if (BIAS) { v0 += bias[col]; v1 += bias[col + 1]; }
                if (RELU) { v0 = fmaxf(v0, 0.f); v1 = fmaxf(v1, 0.f); }
                if (COMBINE) {
                    float2 o = *(const float2*)&other[(size_t)row * N + col];
                    v0 = 0.5f * v0 + 0.5f * o.x;
                    v1 = 0.5f * v1 + 0.5f * o.y;
                }
                if (HALF_OUT) {
                    __half* C = (__half*)Cv;
                    *(__half2*)&C[(size_t)row * N + col] = __floats2half2_rn(v0, v1);
                } else {
                    float* C = (float*)Cv;
                    *(float2*)&C[(size_t)row * N + col] = make_float2(v0, v1);
                }
            }
        }
    }
}

// ---------------- pull aggregation (fp16 gathers): one warp per node -------
template <int F, bool RELU>
__global__ void __launch_bounds__(256) aggh_k(const __half* __restrict__ H,
                                              const float* __restrict__ bias,
                                              float* __restrict__ Out, int n) {
    int gw = (blockIdx.x * 256 + threadIdx.x) >> 5;
    int lane = threadIdx.x & 31;
    if (gw >= n) return;
    constexpr int FPT = F / 32;        // 4 or 2
    const int colb = lane * FPT;
    const float di = g_dinv[gw];

    float acc[FPT];
    if constexpr (FPT == 4) {
        uint2 u = *(const uint2*)&H[(size_t)gw * F + colb];
        float2 p0 = __half22float2(*(__half2*)&u.x);
        float2 p1 = __half22float2(*(__half2*)&u.y);
        acc[0] = di * p0.x; acc[1] = di * p0.y;
        acc[2] = di * p1.x; acc[3] = di * p1.y;
    } else {
        uint32_t u = *(const uint32_t*)&H[(size_t)gw * F + colb];
        float2 p = __half22float2(*(__half2*)&u);
        acc[0] = di * p.x; acc[1] = di * p.y;
    }

    int e = g_rowptr[gw];
    const int end = g_rowptr[gw + 1];
    for (; e < end; e++) {
        int s = __ldg(&g_col[e]);
        float d = __ldg(&g_dinv[s]);
        if constexpr (FPT == 4) {
            uint2 u = *(const uint2*)&H[(size_t)s * F + colb];
            float2 p0 = __half22float2(*(__half2*)&u.x);
            float2 p1 = __half22float2(*(__half2*)&u.y);
            acc[0] += d * p0.x; acc[1] += d * p0.y;
            acc[2] += d * p1.x; acc[3] += d * p1.y;
        } else {
            uint32_t u = *(const uint32_t*)&H[(size_t)s * F + colb];
            float2 p = __half22float2(*(__half2*)&u);
            acc[0] += d * p.x; acc[1] += d * p.y;
        }
    }

#pragma unroll
    for (int j = 0; j < FPT; j++) {
        float o = di * acc[j] + bias[colb + j];
        if (RELU) o = fmaxf(o, 0.f);
        acc[j] = o;
    }
    if constexpr (FPT == 4)
        *(float4*)&Out[(size_t)gw * F + colb] = make_float4(acc[0], acc[1], acc[2], acc[3]);
    else
        *(float2*)&Out[(size_t)gw * F + colb] = make_float2(acc[0], acc[1]);
}

// ---------------- decode: out[q] = dot(z[a], z[b]) over 64 dims ------------
__global__ void __launch_bounds__(256) decode_k(const int* __restrict__ eli,
                                                const float* __restrict__ z,
                                                float* __restrict__ out, int nq) {
    int t = blockIdx.x * 256 + threadIdx.x;
    int q = t >> 4;
    int l = t & 15;
    if (q >= nq) return;
    int a = eli[q];
    int b = eli[nq + q];
    float4 va = *(const float4*)&z[(size_t)a * DOUT + l * 4];
    float4 vb = *(const float4*)&z[(size_t)b * DOUT + l * 4];
    float p = va.x * vb.x + va.y * vb.y + va.z * vb.z + va.w * vb.w;
    p += __shfl_xor_sync(0xffffffffu, p, 8);
    p += __shfl_xor_sync(0xffffffffu, p, 4);
    p += __shfl_xor_sync(0xffffffffu, p, 2);
    p += __shfl_xor_sync(0xffffffffu, p, 1);
    if (l == 0) out[q] = p;
}

// ---------------- launch ----------------------------------------------------
extern "C" void kernel_launch(void* const* d_in, const int* in_sizes, int n_in,
                              void* d_out, int out_size) {
    const float* x   = (const float*)d_in[0];
    const int*   ei  = (const int*)d_in[1];
    const int*   eli = (const int*)d_in[2];
    const float* W1  = (const float*)d_in[3];
    const float* b1  = (const float*)d_in[4];
    const float* W2  = (const float*)d_in[5];
    const float* b2  = (const float*)d_in[6];
    const float* Wf1 = (const float*)d_in[7];
    const float* bf1 = (const float*)d_in[8];
    const float* Wf2 = (const float*)d_in[9];
    const float* bf2 = (const float*)d_in[10];
    float* out = (float*)d_out;

    const int n  = in_sizes[0] / DIN;
    const int ne = in_sizes[1] / 2;
    const int nq = in_sizes[2] / 2;

    __half *pH1h, *pH2h;
    float *pA1, *pG, *pF1, *pZ;
    int* pcnt;
    cudaGetSymbolAddress((void**)&pH1h, g_H1h);
    cudaGetSymbolAddress((void**)&pA1,  g_A1);
    cudaGetSymbolAddress((void**)&pH2h, g_H2h);
    cudaGetSymbolAddress((void**)&pG,   g_G);
    cudaGetSymbolAddress((void**)&pF1,  g_F1);
    cudaGetSymbolAddress((void**)&pZ,   g_Z);
    cudaGetSymbolAddress((void**)&pcnt, g_cnt);

    // 1. CSR build
    cudaMemsetAsync(pcnt, 0, (size_t)n * sizeof(int));
    if ((ne & 3) == 0)
        hist4_k<<<(ne / 4 + 255) / 256, 256>>>(ei + ne, ne);
    else
        hist_k<<<(ne + 255) / 256, 256>>>(ei + ne, ne);
    const int nb = (n + 255) / 256;
    reduce_k<<<nb, 256>>>(n);
    scanb_k<<<1, 256>>>(nb, n);
    scane_k<<<nb, 256>>>(n);
    if ((ne & 3) == 0)
        fill4_k<<<(ne / 4 + 255) / 256, 256>>>(ei, ne);
    else
        fill_k<<<(ne + 255) / 256, 256>>>(ei, ne);

    const int mb = (n + 127) / 128;
    const int ab = (n * 32 + 255) / 256;
    // 2. layer-1 transforms (tf32 tensor cores)
    mmagemm_k<DIN, DHID, 128, false, false, false, true>
        <<<dim3(mb, 1), 256>>>(x, W1, nullptr, nullptr, pH1h, n);
    mmagemm_k<DIN, DFCH, 128, true, true, false, false>
        <<<dim3(mb, 2), 256>>>(x, Wf1, bf1, nullptr, pF1, n);
    // 3. GCN layer 1 aggregation -> A1
    aggh_k<DHID, true><<<ab, 256>>>(pH1h, b1, pA1, n);
    // 4. GCN layer 2
    mmagemm_k<DHID, DOUT, 64, false, false, false, true>
        <<<dim3(mb, 1), 256>>>(pA1, W2, nullptr, nullptr, pH2h, n);
    aggh_k<DOUT, false><<<ab, 256>>>(pH2h, b2, pG, n);
    // 5. FC layer 2 + combine into z
    mmagemm_k<DFCH, DOUT, 64, true, false, true, false>
        <<<dim3(mb, 1), 256>>>(pF1, Wf2, bf2, pG, pZ, n);
    // 6. edge dot-product decode
    decode_k<<<(nq * 16 + 255) / 256, 256>>>(eli, pZ, out, nq);
}

// round 5
// speedup vs baseline: 2.6114x; 1.1091x over previous
#include <cuda_runtime.h>
#include <cuda_fp16.h>
#include <math.h>
#include <stdint.h>

// Problem constants (fixed by the dataset)
#define NN   50000
#define NE   1600000
#define DIN  128
#define DHID 128
#define DOUT 64
#define DFCH 256

// ---------------- scratch (device globals; no allocation allowed) ----------
static __device__ __align__(16) __half g_H1h[NN * DHID];  // x @ W1, fp16
static __device__ __align__(16) __half g_A1h[NN * DHID];  // relu(agg1 + b1), fp16
static __device__ __align__(16) __half g_H2h[NN * DOUT];  // A1 @ W2, fp16
static __device__ __align__(16) float  g_G [NN * DOUT];   // agg2 + b2 (gcn out), fp32
static __device__ __align__(16) __half g_F1h[NN * DFCH];  // relu(x@Wf1+bf1), fp16
static __device__ __align__(16) __half g_Zh[NN * DOUT];   // 0.5*gcn + 0.5*fc, fp16
static __device__ int   g_cnt[NN];
static __device__ int   g_rowptr[NN + 1];
static __device__ int   g_cursor[NN];
static __device__ int   g_col[NE];
static __device__ float g_dinv[NN];
static __device__ int   g_bsum[256];

// ---------------- scan kernels ----------------------------------------------
__global__ void reduce_k(int n) {
    __shared__ int sm[256];
    int t = threadIdx.x;
    int i = blockIdx.x * 256 + t;
    sm[t] = (i < n) ? g_cnt[i] : 0;
    __syncthreads();
    for (int d = 128; d > 0; d >>= 1) {
        if (t < d) sm[t] += sm[t + d];
        __syncthreads();
    }
    if (t == 0) g_bsum[blockIdx.x] = sm[0];
}

__global__ void scanb_k(int nb, int n) {
    __shared__ int sm[256];
    int t = threadIdx.x;
    int v = (t < nb) ? g_bsum[t] : 0;
    sm[t] = v;
    __syncthreads();
    for (int d = 1; d < 256; d <<= 1) {
        int a = (t >= d) ? sm[t - d] : 0;
        __syncthreads();
        sm[t] += a;
        __syncthreads();
    }
    if (t < nb) g_bsum[t] = sm[t] - v;
    if (t == 0) g_rowptr[n] = sm[255];
}

__global__ void scane_k(int n) {
    __shared__ int sm[256];
    int t = threadIdx.x;
    int i = blockIdx.x * 256 + t;
    int v = (i < n) ? g_cnt[i] : 0;
    sm[t] = v;
    __syncthreads();
    for (int d = 1; d < 256; d <<= 1) {
        int a = (t >= d) ? sm[t - d] : 0;
        __syncthreads();
        sm[t] += a;
        __syncthreads();
    }
    if (i < n) {
        int excl = g_bsum[blockIdx.x] + sm[t] - v;
        g_rowptr[i] = excl;
        g_cursor[i] = excl;
        g_dinv[i]   = rsqrtf((float)(v + 1));
    }
}

// ---------------- TF32 helpers ---------------------------------------------
__device__ __forceinline__ float f2tf32(float f) {
    uint32_t u;
    asm("cvt.rna.tf32.f32 %0, %1;" : "=r"(u) : "f"(f));
    return __uint_as_float(u);
}

__device__ __forceinline__ void mma_tf32(float* d, const uint32_t* a, const uint32_t* b) {
    asm volatile(
        "mma.sync.aligned.m16n8k8.row.col.f32.tf32.tf32.f32 "
        "{%0,%1,%2,%3}, {%4,%5,%6,%7}, {%8,%9}, {%0,%1,%2,%3};"
        : "+f"(d[0]), "+f"(d[1]), "+f"(d[2]), "+f"(d[3])
        : "r"(a[0]), "r"(a[1]), "r"(a[2]), "r"(a[3]), "r"(b[0]), "r"(b[1]));
}

// ---------------- TF32 tensor-core GEMM body --------------------------------
// C[nRows x N] = A[nRows x K] @ W[K x N].  BM=128, BK=32, 256 threads.
// Warp layout: 4 (M) x 2 (N). mma m16n8k8.
template <int K, int N, int BN, bool BIAS, bool RELU, bool COMBINE, bool A_HALF, bool HALF_OUT>
__device__ __forceinline__ void gemm_body(const void* Av, const float* __restrict__ W,
                                          const float* __restrict__ bias,
                                          const float* __restrict__ other,
                                          void* __restrict__ Cv, int nRows,
                                          int tileM, int colBlk,
                                          float* As, float* Ws) {
    constexpr int BM = 128, BK = 32;
    constexpr int AS_STRIDE = BK + 4;              // 36: bank = lane for a-frags
    constexpr int WS_STRIDE = BN + 8;              // mod 32 == 8: conflict-free b-frags
    constexpr int NT = BN / 16;                    // n8-tiles per warp (8 or 4)

    const int tid = threadIdx.x;
    const int lane = tid & 31;
    const int wid = tid >> 5;
    const int warpM = wid & 3;
    const int warpN = wid >> 2;
    const int rowBase = tileM * BM;
    const int colBase = colBlk * BN;

    float acc[2][NT][4];
#pragma unroll
    for (int mt = 0; mt < 2; mt++)
#pragma unroll
        for (int nt = 0; nt < NT; nt++)
#pragma unroll
            for (int i = 0; i < 4; i++) acc[mt][nt][i] = 0.f;

    for (int k0 = 0; k0 < K; k0 += BK) {
        // A tile: BM x BK, row-major smem stride 36, tf32-rounded
#pragma unroll
        for (int i = 0; i < 4; i++) {
            int s = tid + i * 256;                 // float4 slot 0..1023
            int m = s >> 3;
            int c4 = (s & 7) * 4;
            float4 v = make_float4(0.f, 0.f, 0.f, 0.f);
            int grow = rowBase + m;
            if (grow < nRows) {
                if (A_HALF) {
                    const __half* Ah = (const __half*)Av;
                    uint2 u = *(const uint2*)&Ah[(size_t)grow * K + k0 + c4];
                    float2 p0 = __half22float2(*(const __half2*)&u.x);
                    float2 p1 = __half22float2(*(const __half2*)&u.y);
                    v = make_float4(p0.x, p0.y, p1.x, p1.y);
                } else {
                    const float* Af = (const float*)Av;
                    v = *(const float4*)&Af[(size_t)grow * K + k0 + c4];
                }
            }
            float* p = &As[m * AS_STRIDE + c4];
            p[0] = f2tf32(v.x); p[1] = f2tf32(v.y);
            p[2] = f2tf32(v.z); p[3] = f2tf32(v.w);
        }
        // W tile: BK x BN, row-major smem stride BN+8, tf32-rounded
#pragma unroll
        for (int i = 0; i < BN / 32; i++) {
            int s = tid + i * 256;
            int r = s / (BN / 4);
            int c4 = (s % (BN / 4)) * 4;
            float4 v = *(const float4*)&W[(size_t)(k0 + r) * N + colBase + c4];
            float* p = &Ws[r * WS_STRIDE + c4];
            p[0] = f2tf32(v.x); p[1] = f2tf32(v.y);
            p[2] = f2tf32(v.z); p[3] = f2tf32(v.w);
        }
        __syncthreads();

#pragma unroll
        for (int ks = 0; ks < BK / 8; ks++) {
            const int k8 = ks * 8;
            uint32_t a[2][4];
#pragma unroll
            for (int mt = 0; mt < 2; mt++) {
                const float* Ap = &As[(warpM * 32 + mt * 16 + (lane >> 2)) * AS_STRIDE
                                      + k8 + (lane & 3)];
                a[mt][0] = __float_as_uint(Ap[0]);
                a[mt][1] = __float_as_uint(Ap[8 * AS_STRIDE]);
                a[mt][2] = __float_as_uint(Ap[4]);
                a[mt][3] = __float_as_uint(Ap[8 * AS_STRIDE + 4]);
            }
#pragma unroll
            for (int nt = 0; nt < NT; nt++) {
                const int n0 = warpN * (NT * 8) + nt * 8 + (lane >> 2);
                uint32_t b[2];
                b[0] = __float_as_uint(Ws[(k8 + (lane & 3)) * WS_STRIDE + n0]);
                b[1] = __float_as_uint(Ws[(k8 + (lane & 3) + 4) * WS_STRIDE + n0]);
                mma_tf32(acc[0][nt], a[0], b);
                mma_tf32(acc[1][nt], a[1], b);
            }
        }
        __syncthreads();
    }

#pragma unroll
    for (int mt = 0; mt < 2; mt++) {
#pragma unroll
        for (int half = 0; half < 2; half++) {
            int row = rowBase + warpM * 32 + mt * 16 + (lane >> 2) + half * 8;
            if (row >= nRows) continue;
#pragma unroll
            for (int nt = 0; nt < NT; nt++) {
                int col = colBase + warpN * (NT * 8) + nt * 8 + (lane & 3) * 2;
                float v0 = acc[mt][nt][half * 2 + 0];
                float v1 = acc[mt][nt][half * 2 + 1];
                if (BIAS) { v0 += bias[col]; v1 += bias[col + 1]; }
                if (RELU) { v0 = fmaxf(v0, 0.f); v1 = fmaxf(v1, 0.f); }
                if (COMBINE) {
                    float2 o = *(const float2*)&other[(size_t)row * N + col];
                    v0 = 0.5f * v0 + 0.5f * o.x;
                    v1 = 0.5f * v1 + 0.5f * o.y;
                }
                if (HALF_OUT) {
                    __half* C = (__half*)Cv;
                    *(__half2*)&C[(size_t)row * N + col] = __floats2half2_rn(v0, v1);
                } else {
                    float* C = (float*)Cv;
                    *(float2*)&C[(size_t)row * N + col] = make_float2(v0, v1);
                }
            }
        }
    }
}

// ---- fused: H1 GEMM tiles (even blocks) || histogram chunks (odd blocks) ---
__global__ void __launch_bounds__(256, 2) h1hist_k(const float* __restrict__ x,
                                                   const float* __restrict__ W1,
                                                   __half* __restrict__ H1,
                                                   const int* __restrict__ dst,
                                                   int ne, int mb, int n) {
    const int role = blockIdx.x & 1;
    const int slot = blockIdx.x >> 1;
    if (role == 1) {                               // histogram chunk
        const int nch = gridDim.x >> 1;
        const int per = (ne + nch - 1) / nch;
        const int s = slot * per;
        const int e = min(s + per, ne);
        for (int i = s + (int)threadIdx.x; i < e; i += 256)
            atomicAdd(&g_cnt[dst[i]], 1);
        return;
    }
    if (slot >= mb) return;
    __shared__ float As[128 * 36];
    __shared__ float Ws[32 * 136];
    gemm_body<DIN, DHID, 128, false, false, false, false, true>(
        x, W1, nullptr, nullptr, H1, n, slot, 0, As, Ws);
}

// ---- fused: F1 GEMM tiles (3 of 4 blocks) || CSR-fill chunks (1 of 4) ------
__global__ void __launch_bounds__(256, 2) f1fill_k(const float* __restrict__ x,
                                                   const float* __restrict__ Wf1,
                                                   const float* __restrict__ bf1,
                                                   __half* __restrict__ F1,
                                                   const int* __restrict__ ei,
                                                   int ne, int mb, int n) {
    const int role = blockIdx.x & 3;
    const int grp  = blockIdx.x >> 2;
    if (role == 3) {                               // fill chunk
        const int nch = gridDim.x >> 2;
        const int per = (ne + nch - 1) / nch;
        const int s = grp * per;
        const int e = min(s + per, ne);
        for (int i = s + (int)threadIdx.x; i < e; i += 256) {
            int sv = ei[i];
            int dv = ei[ne + i];
            g_col[atomicAdd(&g_cursor[dv], 1)] = sv;
        }
        return;
    }
    const int idx = grp * 3 + role;
    if (idx >= 2 * mb) return;
    const int tileM = idx % mb;
    const int colBlk = idx / mb;
    __shared__ float As[128 * 36];
    __shared__ float Ws[32 * 136];
    gemm_body<DIN, DFCH, 128, true, true, false, false, true>(
        x, Wf1, bf1, nullptr, F1, n, tileM, colBlk, As, Ws);
}

// ---- plain GEMM kernels (fp16 A) -------------------------------------------
template <int K, int N, int BN, bool BIAS, bool COMBINE, bool HALF_OUT>
__global__ void __launch_bounds__(256, 2) mmagemm_k(const void* __restrict__ A,
                                                    const float* __restrict__ W,
                                                    const float* __restrict__ bias,
                                                    const float* __restrict__ other,
                                                    void* __restrict__ Cv, int nRows) {
    __shared__ float As[128 * 36];
    __shared__ float Ws[32 * (BN + 8)];
    gemm_body<K, N, BN, BIAS, false, COMBINE, true, HALF_OUT>(
        A, W, bias, other, Cv, nRows, blockIdx.x, blockIdx.y, As, Ws);
}

// ---------------- pull aggregation (fp16 gathers): one warp per node -------
template <int F, bool RELU, bool OUT_HALF>
__global__ void __launch_bounds__(256) aggh_k(const __half* __restrict__ H,
                                              const float* __restrict__ bias,
                                              void* __restrict__ Outv, int n) {
    int gw = (blockIdx.x * 256 + threadIdx.x) >> 5;
    int lane = threadIdx.x & 31;
    if (gw >= n) return;
    constexpr int FPT = F / 32;        // 4 or 2
    const int colb = lane * FPT;
    const float di = g_dinv[gw];

    float acc[FPT];
    if constexpr (FPT == 4) {
        uint2 u = *(const uint2*)&H[(size_t)gw * F + colb];
        float2 p0 = __half22float2(*(const __half2*)&u.x);
        float2 p1 = __half22float2(*(const __half2*)&u.y);
        acc[0] = di * p0.x; acc[1] = di * p0.y;
        acc[2] = di * p1.x; acc[3] = di * p1.y;
    } else {
        uint32_t u = *(const uint32_t*)&H[(size_t)gw * F + colb];
        float2 p = __half22float2(*(const __half2*)&u);
        acc[0] = di * p.x; acc[1] = di * p.y;
    }

    int e = g_rowptr[gw];
    const int end = g_rowptr[gw + 1];
    // 2-way unrolled edge loop for MLP
    for (; e + 1 < end; e += 2) {
        int s0 = __ldg(&g_col[e]);
        int s1 = __ldg(&g_col[e + 1]);
        float d0 = __ldg(&g_dinv[s0]);
        float d1 = __ldg(&g_dinv[s1]);
        if constexpr (FPT == 4) {
            uint2 u0 = *(const uint2*)&H[(size_t)s0 * F + colb];
            uint2 u1 = *(const uint2*)&H[(size_t)s1 * F + colb];
            float2 a0 = __half22float2(*(const __half2*)&u0.x);
            float2 a1 = __half22float2(*(const __half2*)&u0.y);
            float2 b0 = __half22float2(*(const __half2*)&u1.x);
            float2 b1 = __half22float2(*(const __half2*)&u1.y);
            acc[0] += d0 * a0.x + d1 * b0.x;
            acc[1] += d0 * a0.y + d1 * b0.y;
            acc[2] += d0 * a1.x + d1 * b1.x;
            acc[3] += d0 * a1.y + d1 * b1.y;
        } else {
            uint32_t u0 = *(const uint32_t*)&H[(size_t)s0 * F + colb];
            uint32_t u1 = *(const uint32_t*)&H[(size_t)s1 * F + colb];
            float2 a = __half22float2(*(const __half2*)&u0);
            float2 b = __half22float2(*(const __half2*)&u1);
            acc[0] += d0 * a.x + d1 * b.x;
            acc[1] += d0 * a.y + d1 * b.y;
        }
    }
    if (e < end) {
        int s0 = __ldg(&g_col[e]);
        float d0 = __ldg(&g_dinv[s0]);
        if constexpr (FPT == 4) {
            uint2 u0 = *(const uint2*)&H[(size_t)s0 * F + colb];
            float2 a0 = __half22float2(*(const __half2*)&u0.x);
            float2 a1 = __half22float2(*(const __half2*)&u0.y);
            acc[0] += d0 * a0.x; acc[1] += d0 * a0.y;
            acc[2] += d0 * a1.x; acc[3] += d0 * a1.y;
        } else {
            uint32_t u0 = *(const uint32_t*)&H[(size_t)s0 * F + colb];
            float2 a = __half22float2(*(const __half2*)&u0);
            acc[0] += d0 * a.x; acc[1] += d0 * a.y;
        }
    }

#pragma unroll
    for (int j = 0; j < FPT; j++) {
        float o = di * acc[j] + bias[colb + j];
        if (RELU) o = fmaxf(o, 0.f);
        acc[j] = o;
    }
    if constexpr (OUT_HALF) {
        __half* Out = (__half*)Outv;
        if constexpr (FPT == 4) {
            uint2 u;
            *(__half2*)&u.x = __floats2half2_rn(acc[0], acc[1]);
            *(__half2*)&u.y = __floats2half2_rn(acc[2], acc[3]);
            *(uint2*)&Out[(size_t)gw * F + colb] = u;
        } else {
            *(__half2*)&Out[(size_t)gw * F + colb] = __floats2half2_rn(acc[0], acc[1]);
        }
    } else {
        float* Out = (float*)Outv;
        if constexpr (FPT == 4)
            *(float4*)&Out[(size_t)gw * F + colb] = make_float4(acc[0], acc[1], acc[2], acc[3]);
        else
            *(float2*)&Out[(size_t)gw * F + colb] = make_float2(acc[0], acc[1]);
    }
}

// ---------------- decode (fp16 z): out[q] = dot(z[a], z[b]) -----------------
__global__ void __launch_bounds__(256) decodeh_k(const int* __restrict__ eli,
                                                 const __half* __restrict__ zh,
                                                 float* __restrict__ out, int nq) {
    int t = blockIdx.x * 256 + threadIdx.x;
    int q = t >> 4;
    int l = t & 15;
    if (q >= nq) return;
    int a = eli[q];
    int b = eli[nq + q];
    uint2 ua = *(const uint2*)&zh[(size_t)a * DOUT + l * 4];
    uint2 ub = *(const uint2*)&zh[(size_t)b * DOUT + l * 4];
    float2 a0 = __half22float2(*(const __half2*)&ua.x);
    float2 a1 = __half22float2(*(const __half2*)&ua.y);
    float2 b0 = __half22float2(*(const __half2*)&ub.x);
    float2 b1 = __half22float2(*(const __half2*)&ub.y);
    float p = a0.x * b0.x + a0.y * b0.y + a1.x * b1.x + a1.y * b1.y;
    p += __shfl_xor_sync(0xffffffffu, p, 8);
    p += __shfl_xor_sync(0xffffffffu, p, 4);
    p += __shfl_xor_sync(0xffffffffu, p, 2);
    p += __shfl_xor_sync(0xffffffffu, p, 1);
    if (l == 0) out[q] = p;
}

// ---------------- launch ----------------------------------------------------
extern "C" void kernel_launch(void* const* d_in, const int* in_sizes, int n_in,
                              void* d_out, int out_size) {
    const float* x   = (const float*)d_in[0];
    const int*   ei  = (const int*)d_in[1];
    const int*   eli = (const int*)d_in[2];
    const float* W1  = (const float*)d_in[3];
    const float* b1  = (const float*)d_in[4];
    const float* W2  = (const float*)d_in[5];
    const float* b2  = (const float*)d_in[6];
    const float* Wf1 = (const float*)d_in[7];
    const float* bf1 = (const float*)d_in[8];
    const float* Wf2 = (const float*)d_in[9];
    const float* bf2 = (const float*)d_in[10];
    float* out = (float*)d_out;

    const int n  = in_sizes[0] / DIN;
    const int ne = in_sizes[1] / 2;
    const int nq = in_sizes[2] / 2;

    __half *pH1h, *pA1h, *pH2h, *pF1h, *pZh;
    float *pG;
    int* pcnt;
    cudaGetSymbolAddress((void**)&pH1h, g_H1h);
    cudaGetSymbolAddress((void**)&pA1h, g_A1h);
    cudaGetSymbolAddress((void**)&pH2h, g_H2h);
    cudaGetSymbolAddress((void**)&pG,   g_G);
    cudaGetSymbolAddress((void**)&pF1h, g_F1h);
    cudaGetSymbolAddress((void**)&pZh,  g_Zh);
    cudaGetSymbolAddress((void**)&pcnt, g_cnt);

    const int mb = (n + 127) / 128;                 // GEMM row tiles (391)
    const int nb = (n + 255) / 256;                 // scan blocks (196)
    const int ab = (n * 32 + 255) / 256;            // warp-per-node grid

    // 1. zero counts, then [H1 GEMM || histogram] in one striped launch
    cudaMemsetAsync(pcnt, 0, (size_t)n * sizeof(int));
    h1hist_k<<<2 * mb, 256>>>(x, W1, pH1h, ei + ne, ne, mb, n);
    // 2. rowptr scan
    reduce_k<<<nb, 256>>>(n);
    scanb_k<<<1, 256>>>(nb, n);
    scane_k<<<nb, 256>>>(n);
    // 3. [F1 GEMM || CSR fill] in one striped launch
    const int ngrp = (2 * mb + 2) / 3;
    f1fill_k<<<4 * ngrp, 256>>>(x, Wf1, bf1, pF1h, ei, ne, mb, n);
    // 4. GCN layer 1 aggregation -> A1 (fp16)
    aggh_k<DHID, true, true><<<ab, 256>>>(pH1h, b1, pA1h, n);
    // 5. GCN layer 2: H2 = A1 @ W2 (fp16 A)
    mmagemm_k<DHID, DOUT, 64, false, false, true>
        <<<dim3(mb, 1), 256>>>(pA1h, W2, nullptr, nullptr, pH2h, n);
    aggh_k<DOUT, false, false><<<ab, 256>>>(pH2h, b2, pG, n);
    // 6. FC layer 2 + combine into z (fp16): Z = 0.5*(F1@Wf2+bf2) + 0.5*G
    mmagemm_k<DFCH, DOUT, 64, true, true, true>
        <<<dim3(mb, 1), 256>>>(pF1h, Wf2, bf2, pG, pZh, n);
    // 7. edge dot-product decode on fp16 z
    decodeh_k<<<(nq * 16 + 255) / 256, 256>>>(eli, pZh, out, nq);
}